// round 10
// baseline (speedup 1.0000x reference)
#include <cuda_runtime.h>
#include <cstdint>

#define NB    4
#define NPIX  65536     // 256*256
#define CCH   128
#define HF    512
#define WF    512
#define NPTS  8192
#define HID   256
#define NFEAT 129
#define TILE  128       // points per tile in main kernel
#define TPB   2         // tiles per block (sequential, W1 reused)
#define NBIN  4096      // 12-bit radix digit

// ---------------- device scratch (no allocations allowed) ----------------
__device__ unsigned long long g_thresh[NB];
__device__ unsigned long long g_prefix[NB];
__device__ int g_target[NB];
__device__ int g_cnt[NB];
__device__ int g_idx[NB * NPTS];
__device__ unsigned int g_hist[NB * NBIN];   // zero at load; scans re-zero

// 48-bit key: (|v| bits << 16) | idx  -> unique, lexicographic (|v|, idx)
// matches jax top_k(-|v|) selection set including stable tie-break.
__device__ __forceinline__ unsigned long long make_key(float v, int i) {
    unsigned int a = __float_as_uint(v) & 0x7fffffffu;
    return (((unsigned long long)a) << 16) | (unsigned int)i;
}

// ---------------- kernel 0: per-call state reset -------------------------
__global__ void init_kernel() {
    int b = threadIdx.x;
    if (b < NB) { g_prefix[b] = 0ull; g_target[b] = NPTS - 1; g_cnt[b] = 0; }
}

// ---------------- kernel 1a: 12-bit radix histogram (smem-staged) --------
// grid (32, NB) x 256 threads; 8 elems/thread, coalesced.
__global__ void hist_kernel(const float* __restrict__ coarse, int shift) {
    __shared__ unsigned int s_hist[NBIN];
    const int b   = blockIdx.y;
    const int tid = threadIdx.x;
    for (int i = tid; i < NBIN; i += 256) s_hist[i] = 0u;
    __syncthreads();

    const unsigned long long pref = g_prefix[b];
    const float* src = coarse + b * NPIX;
    const int base = blockIdx.x * 2048;
    #pragma unroll
    for (int j = 0; j < 8; j++) {
        const int i = base + j * 256 + tid;
        unsigned long long k = make_key(src[i], i);
        if ((k >> (shift + 12)) == pref)
            atomicAdd(&s_hist[(unsigned int)(k >> shift) & 0xfffu], 1u);
    }
    __syncthreads();

    unsigned int* hist = g_hist + b * NBIN;
    for (int i = tid; i < NBIN; i += 256) {
        unsigned int v = s_hist[i];
        if (v) atomicAdd(&hist[i], v);
    }
}

// ---------------- kernel 1b: scan 4096 bins, locate target, zero hist ----
// grid NB x 1024 threads; uint4-vectorized bin access.
__global__ void scan_kernel(int is_last) {
    __shared__ unsigned int ssum[1024];
    const int b   = blockIdx.x;
    const int tid = threadIdx.x;
    uint4* hist4 = reinterpret_cast<uint4*>(g_hist + b * NBIN);

    const uint4 h = hist4[tid];                      // bins 4*tid .. 4*tid+3
    const unsigned int s = h.x + h.y + h.z + h.w;
    ssum[tid] = s;
    __syncthreads();
    // Hillis-Steele inclusive scan over 1024 partials
    for (int off = 1; off < 1024; off <<= 1) {
        unsigned int v = (tid >= off) ? ssum[tid - off] : 0u;
        __syncthreads();
        ssum[tid] += v;
        __syncthreads();
    }
    const unsigned int incl = ssum[tid];
    const unsigned int excl = incl - s;
    const unsigned int target = (unsigned int)g_target[b];
    if (target >= excl && target < incl) {           // unique owner thread
        unsigned int rem = target - excl;
        int bin = tid * 4;
        unsigned int hv[4] = {h.x, h.y, h.z, h.w};
        #pragma unroll
        for (int i = 0; i < 4; i++) {
            if (rem < hv[i]) break;
            rem -= hv[i]; bin++;
        }
        unsigned long long np = (g_prefix[b] << 12) | (unsigned int)(bin & 0xfff);
        if (is_last) {
            g_thresh[b] = np;                        // full 48-bit key
        } else {
            g_prefix[b] = np;
            g_target[b] = (int)rem;
        }
    }
    // re-zero for next pass / next graph replay
    hist4[tid] = make_uint4(0u, 0u, 0u, 0u);
}

// ---------------- kernel 2: warp-aggregated compaction -------------------
__global__ void compact_kernel(const float* __restrict__ coarse) {
    const int i = blockIdx.x * blockDim.x + threadIdx.x;   // 0..262143
    const int b  = i >> 16;
    const int li = i & 0xffff;
    unsigned long long k = make_key(coarse[i], li);
    const bool take = (k <= g_thresh[b]);
    // warps never straddle a batch (65536 % 32 == 0)
    unsigned mask = __ballot_sync(0xffffffffu, take);
    if (take) {
        const int lane = threadIdx.x & 31;
        const int leader = __ffs(mask) - 1;
        int pos = 0;
        if (lane == leader) pos = atomicAdd(&g_cnt[b], __popc(mask));
        pos = __shfl_sync(0xffffffffu, pos, leader);
        pos += __popc(mask & ((1u << lane) - 1u));
        g_idx[b * NPTS + pos] = li;
    }
}

// ---------------- kernel 3: sample + MLP + scatter ------------------------
// grid (NPTS/TILE/TPB, NB) = (32, 4) -> 128 blocks, one full wave.
// Each block stages W1 once, then processes TPB tiles of 128 points.
#define SMEM_FLOATS (NFEAT * HID + NFEAT * TILE + 32 * TILE)
#define SMEM_BYTES  (SMEM_FLOATS * 4 + TILE * 4)

extern __shared__ float smem[];

__global__ __launch_bounds__(512, 1) void main_kernel(
    const float* __restrict__ coarse, const float* __restrict__ fine,
    const float* __restrict__ W1, const float* __restrict__ b1,
    const float* __restrict__ W2, const float* __restrict__ b2,
    float* __restrict__ out)
{
    float* sW1   = smem;                       // 33024 floats
    float* sF    = sW1 + NFEAT * HID;          // 16512
    float* sPart = sF + NFEAT * TILE;          // 4096
    int*   sIdx  = (int*)(sPart + 32 * TILE);  // 128

    const int tid   = threadIdx.x;
    const int batch = blockIdx.y;

    for (int i = tid; i < NFEAT * HID; i += 512) sW1[i] = W1[i];

    // thread-tile coordinates (fixed across tiles)
    const int hg = tid & 31;       // hidden group (32 groups of 8)
    const int pg = tid >> 5;       // point group  (16 groups of 8)
    const int h0 = hg * 8;
    const int p0 = pg * 8;

    // gather mapping: each thread owns ONE point, 32 channels
    const int gp  = tid & (TILE - 1);          // point owned in gather
    const int gc0 = tid >> 7;                  // first channel (0..3)
    const float* fbase = fine + (size_t)batch * CCH * HF * WF;

    for (int t = 0; t < TPB; t++) {
        const int tile = blockIdx.x * TPB + t;
        __syncthreads();   // sIdx/sF free (previous tile fully consumed) + sW1 ready
        if (tid < TILE) sIdx[tid] = g_idx[batch * NPTS + tile * TILE + tid];
        __syncthreads();

        // ---- sampling: bilinear == 0.25 * (2x2 block at (2r, 2c)) ----
        {
            const int idx = sIdx[gp];
            const int y0 = (idx >> 8) * 2;
            const int x0 = (idx & 255) * 2;
            const float* pptr = fbase + ((size_t)gc0 * HF + y0) * WF + x0;
            float* sdst = sF + gc0 * TILE + gp;
            #pragma unroll 8
            for (int c = 0; c < 32; c++) {      // channels gc0, gc0+4, ...
                float2 r0 = *(const float2*)pptr;
                float2 r1 = *(const float2*)(pptr + WF);
                *sdst = 0.25f * ((r0.x + r0.y) + (r1.x + r1.y));
                pptr += (size_t)4 * HF * WF;
                sdst += 4 * TILE;
            }
        }
        if (tid < TILE) sF[CCH * TILE + tid] = coarse[batch * NPIX + sIdx[tid]];
        __syncthreads();

        // ---- register-blocked fp32 GEMM: hid[256 x 128] ----
        float acc[8][8];
        #pragma unroll
        for (int i = 0; i < 8; i++)
            #pragma unroll
            for (int j = 0; j < 8; j++) acc[i][j] = 0.0f;

        for (int f = 0; f < NFEAT; f++) {
            float4 wa = *(const float4*)&sW1[f * HID + h0];
            float4 wb = *(const float4*)&sW1[f * HID + h0 + 4];
            float4 xa = *(const float4*)&sF[f * TILE + p0];
            float4 xb = *(const float4*)&sF[f * TILE + p0 + 4];
            float w[8] = {wa.x, wa.y, wa.z, wa.w, wb.x, wb.y, wb.z, wb.w};
            float x[8] = {xa.x, xa.y, xa.z, xa.w, xb.x, xb.y, xb.z, xb.w};
            #pragma unroll
            for (int i = 0; i < 8; i++)
                #pragma unroll
                for (int j = 0; j < 8; j++)
                    acc[i][j] += w[i] * x[j];
        }

        // ---- epilogue: relu + W2 dot (partial per hidden-group) ----
        float part[8];
        #pragma unroll
        for (int j = 0; j < 8; j++) part[j] = 0.0f;
        #pragma unroll
        for (int i = 0; i < 8; i++) {
            const int h = h0 + i;
            const float b1v = b1[h];
            const float w2v = W2[h];
            #pragma unroll
            for (int j = 0; j < 8; j++)
                part[j] += fmaxf(acc[i][j] + b1v, 0.0f) * w2v;
        }
        #pragma unroll
        for (int j = 0; j < 8; j++)
            sPart[hg * TILE + p0 + j] = part[j];   // unique slot per (hg, point)
        __syncthreads();

        // ---- deterministic reduce over 32 hidden-groups + scatter ----
        if (tid < TILE) {
            float r = b2[0];
            #pragma unroll
            for (int g = 0; g < 32; g++) r += sPart[g * TILE + tid];
            out[batch * NPIX + sIdx[tid]] = r;
        }
    }
}

// ---------------- launch ---------------------------------------------------
extern "C" void kernel_launch(void* const* d_in, const int* in_sizes, int n_in,
                              void* d_out, int out_size) {
    const float* coarse = (const float*)d_in[0];
    const float* fine   = (const float*)d_in[1];
    const float* W1     = (const float*)d_in[2];
    const float* b1     = (const float*)d_in[3];
    const float* W2     = (const float*)d_in[4];
    const float* b2     = (const float*)d_in[5];
    float* out = (float*)d_out;

    // out = coarse everywhere; refined points overwritten by main_kernel
    cudaMemcpyAsync(out, coarse, (size_t)NB * NPIX * sizeof(float),
                    cudaMemcpyDeviceToDevice, 0);

    init_kernel<<<1, 32>>>();

    // 4-pass 12-bit radix select of the rank-8191 48-bit key
    hist_kernel<<<dim3(32, NB), 256>>>(coarse, 36);
    scan_kernel<<<NB, 1024>>>(0);
    hist_kernel<<<dim3(32, NB), 256>>>(coarse, 24);
    scan_kernel<<<NB, 1024>>>(0);
    hist_kernel<<<dim3(32, NB), 256>>>(coarse, 12);
    scan_kernel<<<NB, 1024>>>(0);
    hist_kernel<<<dim3(32, NB), 256>>>(coarse, 0);
    scan_kernel<<<NB, 1024>>>(1);

    compact_kernel<<<(NB * NPIX) / 256, 256>>>(coarse);

    cudaFuncSetAttribute(main_kernel,
                         cudaFuncAttributeMaxDynamicSharedMemorySize,
                         SMEM_BYTES);
    main_kernel<<<dim3(NPTS / TILE / TPB, NB), 512, SMEM_BYTES>>>(
        coarse, fine, W1, b1, W2, b2, out);
}

// round 11
// speedup vs baseline: 1.0461x; 1.0461x over previous
#include <cuda_runtime.h>
#include <cstdint>

#define NB    4
#define NPIX  65536     // 256*256
#define CCH   128
#define HF    512
#define WF    512
#define NPTS  8192
#define HID   256
#define NFEAT 129
#define TP    64        // points per block in main kernel
#define NBIN  4096      // 12-bit radix digit

// ---------------- device scratch (no allocations allowed) ----------------
__device__ unsigned long long g_thresh[NB];
__device__ unsigned long long g_prefix[NB];
__device__ int g_target[NB];
__device__ int g_cnt[NB];
__device__ int g_idx[NB * NPTS];
__device__ unsigned int g_hist[NB * NBIN];   // zero at load; scans re-zero

// 48-bit key: (|v| bits << 16) | idx  -> unique, lexicographic (|v|, idx)
// matches jax top_k(-|v|) selection set including stable tie-break.
__device__ __forceinline__ unsigned long long make_key(float v, int i) {
    unsigned int a = __float_as_uint(v) & 0x7fffffffu;
    return (((unsigned long long)a) << 16) | (unsigned int)i;
}

// ---------------- kernel 0: per-call state reset -------------------------
__global__ void init_kernel() {
    int b = threadIdx.x;
    if (b < NB) { g_prefix[b] = 0ull; g_target[b] = NPTS - 1; g_cnt[b] = 0; }
}

// ---------------- kernel 1a: 12-bit radix histogram (smem-staged) --------
__global__ void hist_kernel(const float* __restrict__ coarse, int shift) {
    __shared__ unsigned int s_hist[NBIN];
    const int b   = blockIdx.y;
    const int tid = threadIdx.x;
    for (int i = tid; i < NBIN; i += 256) s_hist[i] = 0u;
    __syncthreads();

    const unsigned long long pref = g_prefix[b];
    const float* src = coarse + b * NPIX;
    const int base = blockIdx.x * 2048;
    #pragma unroll
    for (int j = 0; j < 8; j++) {
        const int i = base + j * 256 + tid;
        unsigned long long k = make_key(src[i], i);
        if ((k >> (shift + 12)) == pref)
            atomicAdd(&s_hist[(unsigned int)(k >> shift) & 0xfffu], 1u);
    }
    __syncthreads();

    unsigned int* hist = g_hist + b * NBIN;
    for (int i = tid; i < NBIN; i += 256) {
        unsigned int v = s_hist[i];
        if (v) atomicAdd(&hist[i], v);
    }
}

// ---------------- kernel 1b: scan 4096 bins, locate target, zero hist ----
__global__ void scan_kernel(int is_last) {
    __shared__ unsigned int ssum[1024];
    const int b   = blockIdx.x;
    const int tid = threadIdx.x;
    uint4* hist4 = reinterpret_cast<uint4*>(g_hist + b * NBIN);

    const uint4 h = hist4[tid];                      // bins 4*tid .. 4*tid+3
    const unsigned int s = h.x + h.y + h.z + h.w;
    ssum[tid] = s;
    __syncthreads();
    for (int off = 1; off < 1024; off <<= 1) {
        unsigned int v = (tid >= off) ? ssum[tid - off] : 0u;
        __syncthreads();
        ssum[tid] += v;
        __syncthreads();
    }
    const unsigned int incl = ssum[tid];
    const unsigned int excl = incl - s;
    const unsigned int target = (unsigned int)g_target[b];
    if (target >= excl && target < incl) {           // unique owner thread
        unsigned int rem = target - excl;
        int bin = tid * 4;
        unsigned int hv[4] = {h.x, h.y, h.z, h.w};
        #pragma unroll
        for (int i = 0; i < 4; i++) {
            if (rem < hv[i]) break;
            rem -= hv[i]; bin++;
        }
        unsigned long long np = (g_prefix[b] << 12) | (unsigned int)(bin & 0xfff);
        if (is_last) {
            g_thresh[b] = np;
        } else {
            g_prefix[b] = np;
            g_target[b] = (int)rem;
        }
    }
    hist4[tid] = make_uint4(0u, 0u, 0u, 0u);         // replay-safe
}

// ---------------- kernel 2: warp-aggregated compaction -------------------
__global__ void compact_kernel(const float* __restrict__ coarse) {
    const int i = blockIdx.x * blockDim.x + threadIdx.x;   // 0..262143
    const int b  = i >> 16;
    const int li = i & 0xffff;
    unsigned long long k = make_key(coarse[i], li);
    const bool take = (k <= g_thresh[b]);
    unsigned mask = __ballot_sync(0xffffffffu, take);
    if (take) {
        const int lane = threadIdx.x & 31;
        const int leader = __ffs(mask) - 1;
        int pos = 0;
        if (lane == leader) pos = atomicAdd(&g_cnt[b], __popc(mask));
        pos = __shfl_sync(0xffffffffu, pos, leader);
        pos += __popc(mask & ((1u << lane) - 1u));
        g_idx[b * NPTS + pos] = li;
    }
}

// ---------------- kernel 3: sample + MLP + scatter ------------------------
// grid (NPTS/TP, NB) = (128, 4) = 512 blocks; 256 threads; occ=2.
// Block tile: 64 points x 256 hidden. W1 read via __ldg (L1-resident,
// shared by all blocks); gather uses __ldcg to keep L1 for W1.
__global__ __launch_bounds__(256, 2) void main_kernel(
    const float* __restrict__ coarse, const float* __restrict__ fine,
    const float* __restrict__ W1, const float* __restrict__ b1,
    const float* __restrict__ W2, const float* __restrict__ b2,
    float* __restrict__ out)
{
    __shared__ float sF[NFEAT * TP];     // feats, f-major     (33 KB)
    __shared__ float sPart[32 * TP];     // partial W2 dots    (8 KB)
    __shared__ int   sIdx[TP];

    const int tid   = threadIdx.x;
    const int batch = blockIdx.y;
    const int tile  = blockIdx.x;

    if (tid < TP) sIdx[tid] = g_idx[batch * NPTS + tile * TP + tid];
    __syncthreads();

    // ---- gather: each thread owns one point (tid&63), 32 channels ----
    // bilinear == 0.25 * (2x2 block at (2r, 2c)); .cg -> bypass L1
    {
        const int gp  = tid & (TP - 1);
        const int gc0 = tid >> 6;                  // 0..3
        const int idx = sIdx[gp];
        const int y0 = (idx >> 8) * 2;
        const int x0 = (idx & 255) * 2;
        const float2* pptr = (const float2*)(fine + (size_t)batch * CCH * HF * WF
                                             + ((size_t)gc0 * HF + y0) * WF + x0);
        float* sdst = sF + gc0 * TP + gp;
        #pragma unroll 8
        for (int c = 0; c < 32; c++) {             // channels gc0, gc0+4, ...
            float2 r0 = __ldcg(pptr);
            float2 r1 = __ldcg(pptr + WF / 2);
            *sdst = 0.25f * ((r0.x + r0.y) + (r1.x + r1.y));
            pptr += (size_t)2 * HF * WF;           // 4 channels in float2 units
            sdst += 4 * TP;
        }
    }
    if (tid < TP) sF[CCH * TP + tid] = coarse[batch * NPIX + sIdx[tid]];
    __syncthreads();

    // ---- register GEMM: 256 hidden x 64 points, thread tile 8x8 ----
    const int hg = tid & 31;       // 32 hidden groups of 8
    const int pg = tid >> 5;       // 8 point groups of 8
    const int h0 = hg * 8;
    const int p0 = pg * 8;

    float acc[8][8];
    #pragma unroll
    for (int i = 0; i < 8; i++)
        #pragma unroll
        for (int j = 0; j < 8; j++) acc[i][j] = 0.0f;

    // software pipeline: load f+1 while computing f
    float4 wa = __ldg((const float4*)&W1[0 * HID + h0]);
    float4 wb = __ldg((const float4*)&W1[0 * HID + h0 + 4]);
    float4 xa = *(const float4*)&sF[0 * TP + p0];
    float4 xb = *(const float4*)&sF[0 * TP + p0 + 4];

    for (int f = 0; f < NFEAT; f++) {
        float4 wan, wbn, xan, xbn;
        if (f + 1 < NFEAT) {
            wan = __ldg((const float4*)&W1[(f + 1) * HID + h0]);
            wbn = __ldg((const float4*)&W1[(f + 1) * HID + h0 + 4]);
            xan = *(const float4*)&sF[(f + 1) * TP + p0];
            xbn = *(const float4*)&sF[(f + 1) * TP + p0 + 4];
        }
        const float w[8] = {wa.x, wa.y, wa.z, wa.w, wb.x, wb.y, wb.z, wb.w};
        const float x[8] = {xa.x, xa.y, xa.z, xa.w, xb.x, xb.y, xb.z, xb.w};
        #pragma unroll
        for (int i = 0; i < 8; i++)
            #pragma unroll
            for (int j = 0; j < 8; j++)
                acc[i][j] += w[i] * x[j];
        wa = wan; wb = wbn; xa = xan; xb = xbn;
    }

    // ---- epilogue: relu + W2 dot (partial per hidden-group) ----
    float part[8];
    #pragma unroll
    for (int j = 0; j < 8; j++) part[j] = 0.0f;
    #pragma unroll
    for (int i = 0; i < 8; i++) {
        const int h = h0 + i;
        const float b1v = __ldg(&b1[h]);
        const float w2v = __ldg(&W2[h]);
        #pragma unroll
        for (int j = 0; j < 8; j++)
            part[j] += fmaxf(acc[i][j] + b1v, 0.0f) * w2v;
    }
    #pragma unroll
    for (int j = 0; j < 8; j++)
        sPart[hg * TP + p0 + j] = part[j];   // unique slot per (hg, point)
    __syncthreads();

    // ---- deterministic reduce over 32 hidden-groups + scatter ----
    if (tid < TP) {
        float r = __ldg(&b2[0]);
        #pragma unroll
        for (int g = 0; g < 32; g++) r += sPart[g * TP + tid];
        out[batch * NPIX + sIdx[tid]] = r;
    }
}

// ---------------- launch ---------------------------------------------------
extern "C" void kernel_launch(void* const* d_in, const int* in_sizes, int n_in,
                              void* d_out, int out_size) {
    const float* coarse = (const float*)d_in[0];
    const float* fine   = (const float*)d_in[1];
    const float* W1     = (const float*)d_in[2];
    const float* b1     = (const float*)d_in[3];
    const float* W2     = (const float*)d_in[4];
    const float* b2     = (const float*)d_in[5];
    float* out = (float*)d_out;

    // out = coarse everywhere; refined points overwritten by main_kernel
    cudaMemcpyAsync(out, coarse, (size_t)NB * NPIX * sizeof(float),
                    cudaMemcpyDeviceToDevice, 0);

    init_kernel<<<1, 32>>>();

    // 4-pass 12-bit radix select of the rank-8191 48-bit key
    hist_kernel<<<dim3(32, NB), 256>>>(coarse, 36);
    scan_kernel<<<NB, 1024>>>(0);
    hist_kernel<<<dim3(32, NB), 256>>>(coarse, 24);
    scan_kernel<<<NB, 1024>>>(0);
    hist_kernel<<<dim3(32, NB), 256>>>(coarse, 12);
    scan_kernel<<<NB, 1024>>>(0);
    hist_kernel<<<dim3(32, NB), 256>>>(coarse, 0);
    scan_kernel<<<NB, 1024>>>(1);

    compact_kernel<<<(NB * NPIX) / 256, 256>>>(coarse);

    main_kernel<<<dim3(NPTS / TP, NB), 256>>>(
        coarse, fine, W1, b1, W2, b2, out);
}